// round 5
// baseline (speedup 1.0000x reference)
#include <cuda_runtime.h>
#include <cstdint>

// Problem constants
#define T 4
#define E 250000
#define D 128
#define B 4096
#define L 50

// 128-bit gather with L2 evict_last via cache-policy register (legal at v4 width).
__device__ __forceinline__ float4 ldg4_policy(const float4* p, uint64_t pol) {
    float4 v;
    asm("ld.global.nc.L2::cache_hint.v4.f32 {%0,%1,%2,%3}, [%4], %5;"
        : "=f"(v.x), "=f"(v.y), "=f"(v.z), "=f"(v.w)
        : "l"(p), "l"(pol));
    return v;
}

// Streaming 128-bit store (write-once output; don't pollute L2).
__device__ __forceinline__ void stg_cs4(float4* p, float4 v) {
    asm volatile("st.global.cs.v4.f32 [%0], {%1,%2,%3,%4};"
                 :: "l"(p), "f"(v.x), "f"(v.y), "f"(v.z), "f"(v.w));
}

// One warp per bag (t, b). Lane ln owns float4 at column ln*4.
// __launch_bounds__(256, 8): cap regs at 32 so 8 CTAs (64 warps) co-reside.
__global__ __launch_bounds__(256, 8)
void embbag_kernel(const float4* __restrict__ weights4,
                   const int*    __restrict__ indices,
                   float4*       __restrict__ out4) {
    const int warp_global = (blockIdx.x * blockDim.x + threadIdx.x) >> 5;
    const int lane = threadIdx.x & 31;
    if (warp_global >= T * B) return;

    uint64_t pol;
    asm("createpolicy.fractional.L2::evict_last.b64 %0, 1.0;" : "=l"(pol));

    const int t = warp_global >> 12;        // / B (4096)
    const int b = warp_global & (B - 1);

    const int* __restrict__ idx = indices + ((size_t)t * B + b) * L;

    // Preload all 50 indices: 2 coalesced loads, distribute via shfl.
    const int ia = __ldg(idx + lane);                               // idx[0..31]
    const int ib = (lane < (L - 32)) ? __ldg(idx + 32 + lane) : 0;  // idx[32..49]

    const float4* __restrict__ wt = weights4 + (size_t)t * E * (D / 4);

    float4 a0 = make_float4(0.f, 0.f, 0.f, 0.f);
    float4 a1 = make_float4(0.f, 0.f, 0.f, 0.f);

    // 10 groups of 5 independent LDG.128. Each result is folded into an
    // accumulator immediately after issue of the whole batch, so ptxas can
    // recycle result registers under the 32-reg cap.
    #pragma unroll
    for (int l = 0; l < L; l += 5) {
        const float4* p0;
        const float4* p1;
        const float4* p2;
        const float4* p3;
        const float4* p4;
        {
            const int j0 = (l + 0 < 32) ? __shfl_sync(0xffffffffu, ia, l + 0)
                                        : __shfl_sync(0xffffffffu, ib, l - 32);
            const int j1 = (l + 1 < 32) ? __shfl_sync(0xffffffffu, ia, l + 1)
                                        : __shfl_sync(0xffffffffu, ib, l - 31);
            const int j2 = (l + 2 < 32) ? __shfl_sync(0xffffffffu, ia, l + 2)
                                        : __shfl_sync(0xffffffffu, ib, l - 30);
            const int j3 = (l + 3 < 32) ? __shfl_sync(0xffffffffu, ia, l + 3)
                                        : __shfl_sync(0xffffffffu, ib, l - 29);
            const int j4 = (l + 4 < 32) ? __shfl_sync(0xffffffffu, ia, l + 4)
                                        : __shfl_sync(0xffffffffu, ib, l - 28);
            p0 = wt + (size_t)j0 * (D / 4) + lane;
            p1 = wt + (size_t)j1 * (D / 4) + lane;
            p2 = wt + (size_t)j2 * (D / 4) + lane;
            p3 = wt + (size_t)j3 * (D / 4) + lane;
            p4 = wt + (size_t)j4 * (D / 4) + lane;
        }
        const float4 r0 = ldg4_policy(p0, pol);
        const float4 r1 = ldg4_policy(p1, pol);
        const float4 r2 = ldg4_policy(p2, pol);
        const float4 r3 = ldg4_policy(p3, pol);
        const float4 r4 = ldg4_policy(p4, pol);

        // Consume in issue order, alternating chains -> early reg recycling.
        a0.x += r0.x; a0.y += r0.y; a0.z += r0.z; a0.w += r0.w;
        a1.x += r1.x; a1.y += r1.y; a1.z += r1.z; a1.w += r1.w;
        a0.x += r2.x; a0.y += r2.y; a0.z += r2.z; a0.w += r2.w;
        a1.x += r3.x; a1.y += r3.y; a1.z += r3.z; a1.w += r3.w;
        a0.x += r4.x; a0.y += r4.y; a0.z += r4.z; a0.w += r4.w;
    }

    const float4 acc = make_float4(a0.x + a1.x, a0.y + a1.y,
                                   a0.z + a1.z, a0.w + a1.w);

    // out[b][t*D + lane*4 .. +3], coalesced 512B per warp
    stg_cs4(out4 + ((size_t)b * T + t) * (D / 4) + lane, acc);
}

extern "C" void kernel_launch(void* const* d_in, const int* in_sizes, int n_in,
                              void* d_out, int out_size) {
    const float4* weights4 = (const float4*)d_in[0];  // [T, E, D] fp32
    const int*    indices  = (const int*)d_in[1];     // [T, B, L] int32
    float4*       out4     = (float4*)d_out;          // [B, T*D] fp32

    const int total_warps = T * B;                    // 16384 bags
    const int threads = 256;                          // 8 warps / CTA
    const int blocks = (total_warps * 32) / threads;  // 2048

    embbag_kernel<<<blocks, threads>>>(weights4, indices, out4);
}

// round 6
// speedup vs baseline: 1.0746x; 1.0746x over previous
#include <cuda_runtime.h>
#include <cstdint>

// Problem constants
#define T 4
#define E 250000
#define D 128
#define B 4096
#define L 50

// 128-bit gather with L2 evict_last via cache-policy register.
__device__ __forceinline__ float4 ldg4_policy(const float4* p, uint64_t pol) {
    float4 v;
    asm("ld.global.nc.L2::cache_hint.v4.f32 {%0,%1,%2,%3}, [%4], %5;"
        : "=f"(v.x), "=f"(v.y), "=f"(v.z), "=f"(v.w)
        : "l"(p), "l"(pol));
    return v;
}

// Streaming 128-bit store (write-once output; don't pollute L2).
__device__ __forceinline__ void stg_cs4(float4* p, float4 v) {
    asm volatile("st.global.cs.v4.f32 [%0], {%1,%2,%3,%4};"
                 :: "l"(p), "f"(v.x), "f"(v.y), "f"(v.z), "f"(v.w));
}

// Single-wave table-phased kernel: 512 CTAs (all co-resident), warp w = bag b.
// All CTAs sweep table 0, then 1, ... so the live weight working set is ONE
// table's unique rows (~72MB), which fits L2 (126MB) -> repeats hit L2.
__global__ __launch_bounds__(256, 4)
void embbag_kernel(const float4* __restrict__ weights4,
                   const int*    __restrict__ indices,
                   float4*       __restrict__ out4) {
    const int b = (blockIdx.x * blockDim.x + threadIdx.x) >> 5;  // bag = warp id
    const int lane = threadIdx.x & 31;
    if (b >= B) return;

    uint64_t pol;
    asm("createpolicy.fractional.L2::evict_last.b64 %0, 1.0;" : "=l"(pol));

    #pragma unroll
    for (int t = 0; t < T; t++) {
        const int* __restrict__ idx = indices + ((size_t)t * B + b) * L;

        // Preload all 50 indices: 2 coalesced loads, distribute via shfl.
        const int ia = __ldg(idx + lane);                               // idx[0..31]
        const int ib = (lane < (L - 32)) ? __ldg(idx + 32 + lane) : 0;  // idx[32..49]

        const float4* __restrict__ wt = weights4 + (size_t)t * E * (D / 4);

        float4 a0 = make_float4(0.f, 0.f, 0.f, 0.f);
        float4 a1 = make_float4(0.f, 0.f, 0.f, 0.f);

        // 5 groups of 10 fully independent LDG.128 -> ~10 outstanding loads
        // per warp (we only have ~28 warps/SM in this single-wave config,
        // so per-warp MLP carries the latency hiding).
        #pragma unroll
        for (int l = 0; l < L; l += 10) {
            const float4* p[10];
            #pragma unroll
            for (int k = 0; k < 10; k++) {
                const int ll = l + k;       // compile-time resolvable selector
                const int j = (ll < 32) ? __shfl_sync(0xffffffffu, ia, ll)
                                        : __shfl_sync(0xffffffffu, ib, ll - 32);
                p[k] = wt + (size_t)j * (D / 4) + lane;
            }
            float4 r[10];
            #pragma unroll
            for (int k = 0; k < 10; k++) r[k] = ldg4_policy(p[k], pol);

            #pragma unroll
            for (int k = 0; k < 10; k += 2) {
                a0.x += r[k].x;   a0.y += r[k].y;   a0.z += r[k].z;   a0.w += r[k].w;
                a1.x += r[k+1].x; a1.y += r[k+1].y; a1.z += r[k+1].z; a1.w += r[k+1].w;
            }
        }

        const float4 acc = make_float4(a0.x + a1.x, a0.y + a1.y,
                                       a0.z + a1.z, a0.w + a1.w);

        // out[b][t*D + lane*4 .. +3], coalesced 512B per warp
        stg_cs4(out4 + ((size_t)b * T + t) * (D / 4) + lane, acc);
    }
}

extern "C" void kernel_launch(void* const* d_in, const int* in_sizes, int n_in,
                              void* d_out, int out_size) {
    const float4* weights4 = (const float4*)d_in[0];  // [T, E, D] fp32
    const int*    indices  = (const int*)d_in[1];     // [T, B, L] int32
    float4*       out4     = (float4*)d_out;          // [B, T*D] fp32

    // 4096 bags, one warp each -> 512 CTAs of 8 warps: fits in a single wave
    // on 148 SMs, so all CTAs march through tables in (loose) lockstep.
    const int threads = 256;
    const int blocks = (B * 32) / threads;            // 512
    embbag_kernel<<<blocks, threads>>>(weights4, indices, out4);
}